// round 5
// baseline (speedup 1.0000x reference)
#include <cuda_runtime.h>

#define N_NODES 160000
#define NODES_PER_GRAPH 20000
#define N_GRAPHS 8
#define N_EDGES 5120000
#define HID 16
#define O1 4000
#define O2 800
#define O3 160
#define NOUT 10

// -------- scratch (device globals: no allocation allowed) ----------------
// agg arrays obey a zero-invariant: zero at entry to every kernel_launch
// (zero-initialized at load; k_node1/k_node2 reset them after consuming).
__device__ __align__(16) float d_agg1[N_NODES];
__device__ __align__(16) float d_agg2[N_NODES];
__device__ __align__(16) float d_p[N_NODES];
__device__ __align__(16) float d_q[N_NODES];
// batch-major activations: [b][k]
__device__ __align__(16) float d_g[N_GRAPHS * NODES_PER_GRAPH];
__device__ __align__(16) float d_h1[N_GRAPHS * O1];
__device__ __align__(16) float d_h2[N_GRAPHS * O2];
__device__ __align__(16) float d_h3[N_GRAPHS * O3];

// -------- scalar edge scatter: agg[tgt] += ew * val[src] -----------------
__global__ void k_scatter(const int* __restrict__ src, const int* __restrict__ tgt,
                          const float* __restrict__ ew, const float* __restrict__ val_in,
                          int pass) {
    const float* __restrict__ val = (pass == 0) ? val_in : d_p;
    float* __restrict__ agg = (pass == 0) ? d_agg1 : d_agg2;
    int t = blockIdx.x * blockDim.x + threadIdx.x;
    int e0 = t * 4;
    if (e0 + 3 < N_EDGES) {
        int4   s = *reinterpret_cast<const int4*>(src + e0);
        int4   g = *reinterpret_cast<const int4*>(tgt + e0);
        float4 w = *reinterpret_cast<const float4*>(ew + e0);
        atomicAdd(&agg[g.x], w.x * __ldg(&val[s.x]));
        atomicAdd(&agg[g.y], w.y * __ldg(&val[s.y]));
        atomicAdd(&agg[g.z], w.z * __ldg(&val[s.z]));
        atomicAdd(&agg[g.w], w.w * __ldg(&val[s.w]));
    } else if (e0 < N_EDGES) {
        for (int e = e0; e < N_EDGES; e++)
            atomicAdd(&agg[tgt[e]], ew[e] * __ldg(&val[src[e]]));
    }
}

// -------- per-node layer-1 + fold layer-2 matmuls to scalars -------------
__global__ void k_node1(const float* __restrict__ x,
                        const float* __restrict__ Wr1, const float* __restrict__ br1,
                        const float* __restrict__ Ws1, const float* __restrict__ Wr2,
                        const float* __restrict__ Ws2) {
    __shared__ float swr1[HID], sbr1[HID], sws1[HID], swr2[HID], sws2[HID];
    if (threadIdx.x < HID) {
        swr1[threadIdx.x] = Wr1[threadIdx.x];
        sbr1[threadIdx.x] = br1[threadIdx.x];
        sws1[threadIdx.x] = Ws1[threadIdx.x];
        swr2[threadIdx.x] = Wr2[threadIdx.x];
        sws2[threadIdx.x] = Ws2[threadIdx.x];
    }
    __syncthreads();
    int n = blockIdx.x * blockDim.x + threadIdx.x;
    if (n >= N_NODES) return;
    float a = d_agg1[n];
    d_agg1[n] = 0.f;                      // restore zero-invariant for next replay
    float xv = x[n];
    float p = 0.f, q = 0.f;
#pragma unroll
    for (int f = 0; f < HID; f++) {
        float h = fmaf(a, swr1[f], fmaf(xv, sws1[f], sbr1[f]));
        h = fmaxf(h, 0.f);
        p = fmaf(swr2[f], h, p);
        q = fmaf(sws2[f], h, q);
    }
    d_p[n] = p;
    d_q[n] = q;
}

// -------- per-node layer-2 epilogue; write g batch-major [b][i] ----------
__global__ void k_node2(const float* __restrict__ br2) {
    int n = blockIdx.x * blockDim.x + threadIdx.x;
    if (n >= N_NODES) return;
    float h2 = d_agg2[n] + __ldg(br2) + d_q[n];
    d_agg2[n] = 0.f;                      // restore zero-invariant
    int b = n / NODES_PER_GRAPH;
    int i = n - b * NODES_PER_GRAPH;
    d_g[b * NODES_PER_GRAPH + i] = h2;    // coalesced: i == n mod 20000
}

// -------- dense layer: out[b][o] = act( sum_k W[o][k]*in[b][k] + bias[o] )
// One block owns 8 output rows x 8 batches; each thread owns 4 consecutive k
// (stride 1024). ALL loads lane-contiguous LDG.128 (4 wavefronts each).
// K must be a multiple of 4.
template <bool RELU>
__global__ void __launch_bounds__(256, 2)
k_gemm8(const float* __restrict__ W, const float* __restrict__ bias,
        const float* __restrict__ in, float* __restrict__ out, int K, int M) {
    const int tid = threadIdx.x;
    const int o0 = blockIdx.x * 8;
    float acc[8][8];
#pragma unroll
    for (int r = 0; r < 8; r++)
#pragma unroll
        for (int b = 0; b < 8; b++) acc[r][b] = 0.f;

    const float* Wb = W + (size_t)o0 * K;
    for (int k0 = tid * 4; k0 < K; k0 += 1024) {
        float4 w[8];
#pragma unroll
        for (int r = 0; r < 8; r++)
            w[r] = *reinterpret_cast<const float4*>(Wb + (size_t)r * K + k0);
#pragma unroll
        for (int b = 0; b < 8; b++) {
            float4 g = *reinterpret_cast<const float4*>(in + (size_t)b * K + k0);
#pragma unroll
            for (int r = 0; r < 8; r++) {
                acc[r][b] = fmaf(w[r].x, g.x, acc[r][b]);
                acc[r][b] = fmaf(w[r].y, g.y, acc[r][b]);
                acc[r][b] = fmaf(w[r].z, g.z, acc[r][b]);
                acc[r][b] = fmaf(w[r].w, g.w, acc[r][b]);
            }
        }
    }

    // staged shared-memory reduction of 64 accumulators over 256 threads
    __shared__ float s[32 * 256];  // 32 KB
#pragma unroll
    for (int half = 0; half < 2; half++) {
        __syncthreads();
#pragma unroll
        for (int j = 0; j < 32; j++) {
            int idx = half * 32 + j;
            s[j * 256 + tid] = acc[idx >> 3][idx & 7];
        }
        __syncthreads();
        int j = tid >> 3;      // 0..31 : which value
        int part = tid & 7;    // 0..7  : which slice of 256 partials
        float v = 0.f;
#pragma unroll
        for (int t = 0; t < 32; t++) v += s[j * 256 + part + t * 8];
        v += __shfl_down_sync(0xffffffffu, v, 4, 8);
        v += __shfl_down_sync(0xffffffffu, v, 2, 8);
        v += __shfl_down_sync(0xffffffffu, v, 1, 8);
        if (part == 0) {
            int idx = half * 32 + j;
            int r = idx >> 3, b = idx & 7;
            float o = v + __ldg(&bias[o0 + r]);
            if (RELU) o = fmaxf(o, 0.f);
            out[(size_t)b * M + o0 + r] = o;
        }
    }
}

// -------- final 10x160 layer + log_softmax (h3 batch-major) --------------
__global__ void k_final(const float* __restrict__ W4, const float* __restrict__ b4,
                        float* __restrict__ out) {
    __shared__ float logits[N_GRAPHS][NOUT];
    int tid = threadIdx.x;
    if (tid < N_GRAPHS * NOUT) {
        int o = tid / N_GRAPHS;
        int b = tid % N_GRAPHS;
        float v = __ldg(&b4[o]);
        for (int k = 0; k < O3; k++)
            v = fmaf(__ldg(&W4[o * O3 + k]), d_h3[b * O3 + k], v);
        logits[b][o] = v;
    }
    __syncthreads();
    if (tid < N_GRAPHS) {
        float m = -1e30f;
#pragma unroll
        for (int o = 0; o < NOUT; o++) m = fmaxf(m, logits[tid][o]);
        float sum = 0.f;
#pragma unroll
        for (int o = 0; o < NOUT; o++) sum += expf(logits[tid][o] - m);
        float lse = m + logf(sum);
#pragma unroll
        for (int o = 0; o < NOUT; o++) out[tid * NOUT + o] = logits[tid][o] - lse;
    }
}

void launch_gemms(const float* W1, const float* b1, const float* W2, const float* b2,
                  const float* W3, const float* b3, const float* W4, const float* b4,
                  float* out) {
    static float *p_g = nullptr, *p_h1 = nullptr, *p_h2 = nullptr, *p_h3 = nullptr;
    if (!p_g) {
        cudaGetSymbolAddress((void**)&p_g,  d_g);
        cudaGetSymbolAddress((void**)&p_h1, d_h1);
        cudaGetSymbolAddress((void**)&p_h2, d_h2);
        cudaGetSymbolAddress((void**)&p_h3, d_h3);
    }
    k_gemm8<true ><<<O1 / 8, 256>>>(W1, b1, p_g,  p_h1, NODES_PER_GRAPH, O1);
    k_gemm8<true ><<<O2 / 8, 256>>>(W2, b2, p_h1, p_h2, O1, O2);
    k_gemm8<true ><<<O3 / 8, 256>>>(W3, b3, p_h2, p_h3, O2, O3);
    k_final<<<1, 128>>>(W4, b4, out);
}

extern "C" void kernel_launch(void* const* d_in, const int* in_sizes, int n_in,
                              void* d_out, int out_size) {
    const float* x   = (const float*)d_in[0];
    const float* ew  = (const float*)d_in[1];
    const float* Wr1 = (const float*)d_in[2];
    const float* br1 = (const float*)d_in[3];
    const float* Ws1 = (const float*)d_in[4];
    const float* Wr2 = (const float*)d_in[5];
    const float* br2 = (const float*)d_in[6];
    const float* Ws2 = (const float*)d_in[7];
    const float* W1  = (const float*)d_in[8];
    const float* b1  = (const float*)d_in[9];
    const float* W2  = (const float*)d_in[10];
    const float* b2  = (const float*)d_in[11];
    const float* W3  = (const float*)d_in[12];
    const float* b3  = (const float*)d_in[13];
    const float* W4  = (const float*)d_in[14];
    const float* b4  = (const float*)d_in[15];
    const int*   ei  = (const int*)d_in[16];
    float* out = (float*)d_out;

    const int* src = ei;
    const int* tgt = ei + N_EDGES;

    const int NODE_BLOCKS = (N_NODES + 255) / 256;
    const int EDGE_BLOCKS = (N_EDGES / 4 + 255) / 256;

    k_scatter<<<EDGE_BLOCKS, 256>>>(src, tgt, ew, x, 0);
    k_node1<<<NODE_BLOCKS, 256>>>(x, Wr1, br1, Ws1, Wr2, Ws2);
    k_scatter<<<EDGE_BLOCKS, 256>>>(src, tgt, ew, nullptr, 1);
    k_node2<<<NODE_BLOCKS, 256>>>(br2);

    launch_gemms(W1, b1, W2, b2, W3, b3, W4, b4, out);
}

// round 7
// speedup vs baseline: 1.4484x; 1.4484x over previous
#include <cuda_runtime.h>

#define N_NODES 160000
#define NODES_PER_GRAPH 20000
#define N_GRAPHS 8
#define N_EDGES 5120000
#define HID 16
#define O1 4000
#define O2 800
#define O3 160
#define NOUT 10

// -------- scratch (device globals: no allocation allowed) ----------------
// agg arrays obey a zero-invariant: zero at entry to every kernel_launch
// (zero-initialized at load; k_node1/k_node2 reset them after consuming).
__device__ __align__(16) float d_agg1[N_NODES];
__device__ __align__(16) float d_agg2[N_NODES];
__device__ __align__(16) float d_p[N_NODES];
__device__ __align__(16) float d_q[N_NODES];
// batch-major activations: [b][k]
__device__ __align__(16) float d_g[N_GRAPHS * NODES_PER_GRAPH];
__device__ __align__(16) float d_h1[N_GRAPHS * O1];
__device__ __align__(16) float d_h2[N_GRAPHS * O2];
__device__ __align__(16) float d_h3[N_GRAPHS * O3];

// -------- scalar edge scatter: agg[tgt] += ew * val[src] -----------------
__global__ void k_scatter(const int* __restrict__ src, const int* __restrict__ tgt,
                          const float* __restrict__ ew, const float* __restrict__ val_in,
                          int pass) {
    const float* __restrict__ val = (pass == 0) ? val_in : d_p;
    float* __restrict__ agg = (pass == 0) ? d_agg1 : d_agg2;
    int t = blockIdx.x * blockDim.x + threadIdx.x;
    int e0 = t * 4;
    if (e0 + 3 < N_EDGES) {
        int4   s = *reinterpret_cast<const int4*>(src + e0);
        int4   g = *reinterpret_cast<const int4*>(tgt + e0);
        float4 w = *reinterpret_cast<const float4*>(ew + e0);
        atomicAdd(&agg[g.x], w.x * __ldg(&val[s.x]));
        atomicAdd(&agg[g.y], w.y * __ldg(&val[s.y]));
        atomicAdd(&agg[g.z], w.z * __ldg(&val[s.z]));
        atomicAdd(&agg[g.w], w.w * __ldg(&val[s.w]));
    } else if (e0 < N_EDGES) {
        for (int e = e0; e < N_EDGES; e++)
            atomicAdd(&agg[tgt[e]], ew[e] * __ldg(&val[src[e]]));
    }
}

// -------- per-node layer-1 (float4, grid-stride) -------------------------
__global__ void k_node1(const float* __restrict__ x,
                        const float* __restrict__ Wr1, const float* __restrict__ br1,
                        const float* __restrict__ Ws1, const float* __restrict__ Wr2,
                        const float* __restrict__ Ws2) {
    __shared__ float swr1[HID], sbr1[HID], sws1[HID], swr2[HID], sws2[HID];
    if (threadIdx.x < HID) {
        swr1[threadIdx.x] = Wr1[threadIdx.x];
        sbr1[threadIdx.x] = br1[threadIdx.x];
        sws1[threadIdx.x] = Ws1[threadIdx.x];
        swr2[threadIdx.x] = Wr2[threadIdx.x];
        sws2[threadIdx.x] = Ws2[threadIdx.x];
    }
    __syncthreads();
    int t = blockIdx.x * blockDim.x + threadIdx.x;
    int n0 = t * 4;
    if (n0 >= N_NODES) return;
    float4 a  = *reinterpret_cast<float4*>(&d_agg1[n0]);
    float4 xv = *reinterpret_cast<const float4*>(&x[n0]);
    *reinterpret_cast<float4*>(&d_agg1[n0]) = make_float4(0.f, 0.f, 0.f, 0.f);
    float av[4] = {a.x, a.y, a.z, a.w};
    float xa[4] = {xv.x, xv.y, xv.z, xv.w};
    float pv[4], qv[4];
#pragma unroll
    for (int j = 0; j < 4; j++) {
        float p = 0.f, q = 0.f;
#pragma unroll
        for (int f = 0; f < HID; f++) {
            float h = fmaf(av[j], swr1[f], fmaf(xa[j], sws1[f], sbr1[f]));
            h = fmaxf(h, 0.f);
            p = fmaf(swr2[f], h, p);
            q = fmaf(sws2[f], h, q);
        }
        pv[j] = p; qv[j] = q;
    }
    *reinterpret_cast<float4*>(&d_p[n0]) = make_float4(pv[0], pv[1], pv[2], pv[3]);
    *reinterpret_cast<float4*>(&d_q[n0]) = make_float4(qv[0], qv[1], qv[2], qv[3]);
}

// -------- per-node layer-2 epilogue; write g batch-major [b][i] ----------
// NODES_PER_GRAPH % 4 == 0 so a float4 never straddles a graph boundary.
__global__ void k_node2(const float* __restrict__ br2) {
    int t = blockIdx.x * blockDim.x + threadIdx.x;
    int n0 = t * 4;
    if (n0 >= N_NODES) return;
    float b2 = __ldg(br2);
    float4 a = *reinterpret_cast<float4*>(&d_agg2[n0]);
    float4 q = *reinterpret_cast<float4*>(&d_q[n0]);
    *reinterpret_cast<float4*>(&d_agg2[n0]) = make_float4(0.f, 0.f, 0.f, 0.f);
    float4 h = make_float4(a.x + b2 + q.x, a.y + b2 + q.y,
                           a.z + b2 + q.z, a.w + b2 + q.w);
    // d_g is batch-major [b][i] and n -> (b, i) is the identity on flat index
    *reinterpret_cast<float4*>(&d_g[n0]) = h;
}

// -------- dense layer: out[b][o] = act( sum_k W[o][k]*in[b][k] + bias[o] )
// 8 output rows x 8 batches per block. Single base pointer + compile-time
// row offsets so every load is LDG.128 with immediate offset (2 addr regs).
// KROW = K as a compile-time constant to enable immediate offsets.
template <bool RELU, int K>
__global__ void __launch_bounds__(256)
k_gemm8(const float* __restrict__ W, const float* __restrict__ bias,
        const float* __restrict__ in, float* __restrict__ out, int M) {
    const int tid = threadIdx.x;
    const int o0 = blockIdx.x * 8;
    float acc[8][8];
#pragma unroll
    for (int r = 0; r < 8; r++)
#pragma unroll
        for (int b = 0; b < 8; b++) acc[r][b] = 0.f;

    const float* Wp = W + (size_t)o0 * K + tid * 4;
    const float* gp = in + tid * 4;
#pragma unroll 1
    for (int k0 = tid * 4; k0 < K; k0 += 1024, Wp += 1024, gp += 1024) {
        float4 w[8];
#pragma unroll
        for (int r = 0; r < 8; r++)
            w[r] = *reinterpret_cast<const float4*>(Wp + r * K);   // imm offset
#pragma unroll
        for (int b = 0; b < 8; b++) {
            float4 g = *reinterpret_cast<const float4*>(gp + b * K); // imm offset
#pragma unroll
            for (int r = 0; r < 8; r++) {
                acc[r][b] = fmaf(w[r].x, g.x, acc[r][b]);
                acc[r][b] = fmaf(w[r].y, g.y, acc[r][b]);
                acc[r][b] = fmaf(w[r].z, g.z, acc[r][b]);
                acc[r][b] = fmaf(w[r].w, g.w, acc[r][b]);
            }
        }
    }

    // staged shared-memory reduction of 64 accumulators over 256 threads
    __shared__ float s[32 * 256];  // 32 KB
#pragma unroll
    for (int half = 0; half < 2; half++) {
        __syncthreads();
#pragma unroll
        for (int j = 0; j < 32; j++) {
            int idx = half * 32 + j;
            s[j * 256 + tid] = acc[idx >> 3][idx & 7];
        }
        __syncthreads();
        int j = tid >> 3;      // 0..31 : which value
        int part = tid & 7;    // 0..7  : which slice of 256 partials
        float v = 0.f;
#pragma unroll
        for (int t = 0; t < 32; t++) v += s[j * 256 + part + t * 8];
        v += __shfl_down_sync(0xffffffffu, v, 4, 8);
        v += __shfl_down_sync(0xffffffffu, v, 2, 8);
        v += __shfl_down_sync(0xffffffffu, v, 1, 8);
        if (part == 0) {
            int idx = half * 32 + j;
            int r = idx >> 3, b = idx & 7;
            float o = v + __ldg(&bias[o0 + r]);
            if (RELU) o = fmaxf(o, 0.f);
            out[(size_t)b * M + o0 + r] = o;
        }
    }
}

// -------- final 10x160 layer + log_softmax (h3 batch-major) --------------
__global__ void k_final(const float* __restrict__ W4, const float* __restrict__ b4,
                        float* __restrict__ out) {
    __shared__ float logits[N_GRAPHS][NOUT];
    int tid = threadIdx.x;
    if (tid < N_GRAPHS * NOUT) {
        int o = tid / N_GRAPHS;
        int b = tid % N_GRAPHS;
        float v = __ldg(&b4[o]);
        for (int k = 0; k < O3; k++)
            v = fmaf(__ldg(&W4[o * O3 + k]), d_h3[b * O3 + k], v);
        logits[b][o] = v;
    }
    __syncthreads();
    if (tid < N_GRAPHS) {
        float m = -1e30f;
#pragma unroll
        for (int o = 0; o < NOUT; o++) m = fmaxf(m, logits[tid][o]);
        float sum = 0.f;
#pragma unroll
        for (int o = 0; o < NOUT; o++) sum += expf(logits[tid][o] - m);
        float lse = m + logf(sum);
#pragma unroll
        for (int o = 0; o < NOUT; o++) out[tid * NOUT + o] = logits[tid][o] - lse;
    }
}

void launch_gemms(const float* W1, const float* b1, const float* W2, const float* b2,
                  const float* W3, const float* b3, const float* W4, const float* b4,
                  float* out) {
    static float *p_g = nullptr, *p_h1 = nullptr, *p_h2 = nullptr, *p_h3 = nullptr;
    if (!p_g) {
        cudaGetSymbolAddress((void**)&p_g,  d_g);
        cudaGetSymbolAddress((void**)&p_h1, d_h1);
        cudaGetSymbolAddress((void**)&p_h2, d_h2);
        cudaGetSymbolAddress((void**)&p_h3, d_h3);
    }
    k_gemm8<true, NODES_PER_GRAPH><<<O1 / 8, 256>>>(W1, b1, p_g,  p_h1, O1);
    k_gemm8<true, O1             ><<<O2 / 8, 256>>>(W2, b2, p_h1, p_h2, O2);
    k_gemm8<true, O2             ><<<O3 / 8, 256>>>(W3, b3, p_h2, p_h3, O3);
    k_final<<<1, 128>>>(W4, b4, out);
}

extern "C" void kernel_launch(void* const* d_in, const int* in_sizes, int n_in,
                              void* d_out, int out_size) {
    const float* x   = (const float*)d_in[0];
    const float* ew  = (const float*)d_in[1];
    const float* Wr1 = (const float*)d_in[2];
    const float* br1 = (const float*)d_in[3];
    const float* Ws1 = (const float*)d_in[4];
    const float* Wr2 = (const float*)d_in[5];
    const float* br2 = (const float*)d_in[6];
    const float* Ws2 = (const float*)d_in[7];
    const float* W1  = (const float*)d_in[8];
    const float* b1  = (const float*)d_in[9];
    const float* W2  = (const float*)d_in[10];
    const float* b2  = (const float*)d_in[11];
    const float* W3  = (const float*)d_in[12];
    const float* b3  = (const float*)d_in[13];
    const float* W4  = (const float*)d_in[14];
    const float* b4  = (const float*)d_in[15];
    const int*   ei  = (const int*)d_in[16];
    float* out = (float*)d_out;

    const int* src = ei;
    const int* tgt = ei + N_EDGES;

    const int NODE4_BLOCKS = (N_NODES / 4 + 255) / 256;   // 157
    const int EDGE_BLOCKS  = (N_EDGES / 4 + 255) / 256;   // 5000

    k_scatter<<<EDGE_BLOCKS, 256>>>(src, tgt, ew, x, 0);
    k_node1<<<NODE4_BLOCKS, 256>>>(x, Wr1, br1, Ws1, Wr2, Ws2);
    k_scatter<<<EDGE_BLOCKS, 256>>>(src, tgt, ew, nullptr, 1);
    k_node2<<<NODE4_BLOCKS, 256>>>(br2);

    launch_gemms(W1, b1, W2, b2, W3, b3, W4, b4, out);
}